// round 14
// baseline (speedup 1.0000x reference)
#include <cuda_runtime.h>
#include <cuda_fp16.h>
#include <cstdint>

// Problem constants
#define D_DIM   1024
#define E_DIM   64
#define TOPK    8
#define B_DIM   4
#define ALPHA   0.1f
#define EPS_R   1e-20f

#define THREADS 256
#define TPB     128              // tokens per CTA (one tile per CTA)
#define KC      64               // K per chunk
#define NCHUNK  (D_DIM / KC)     // 16

#define W_SCALE    65536.0f      // 2^16: keeps w2 split term normal in fp16
#define W_UNSCALE  1.52587890625e-05f   // 2^-16 (exact)

// smem: fp16 tiles, 64 cols used, row stride 72 el = 144 B (conflict-free ldmatrix)
#define STR_B   144
#define XT_B    (TPB * STR_B)         // 18432
#define WT_B    (E_DIM * STR_B)       // 9216
#define OFF_X1  0
#define OFF_X2  (OFF_X1 + XT_B)
#define OFF_W1  (OFF_X2 + XT_B)
#define OFF_W2  (OFF_W1 + WT_B)
#define BUF_B   (OFF_W2 + WT_B)       // 55296 per buffer
#define SMEM_BYTES (2 * BUF_B)        // 110592 per CTA (x2 CTA/SM ~ 221KB)
#define LOG_STR 66                    // padded logits row (floats)

// device-global scratch (static — no allocation)
__device__ uint16_t g_ws[2 * E_DIM * D_DIM];   // pre-split scaled W (fp16 bits)
__device__ float g_ce[B_DIM * E_DIM];
__device__ float g_ssum[B_DIM * E_DIM];
__device__ unsigned int g_count;

// ------------------------- helpers -------------------------
__device__ __forceinline__ void split2h(float v, uint32_t& a, uint32_t& b) {
    __half h1 = __float2half_rn(v);
    float r = v - __half2float(h1);
    __half h2 = __float2half_rn(r);
    a = __half_as_ushort(h1);
    b = __half_as_ushort(h2);
}

__device__ __forceinline__ void store_split_f4(char* sm, uint32_t byte_off, float4 v) {
    uint32_t a0,b0,a1,b1,a2,b2,a3,b3;
    split2h(v.x,a0,b0); split2h(v.y,a1,b1);
    split2h(v.z,a2,b2); split2h(v.w,a3,b3);
    *(uint2*)(sm + OFF_X1 + byte_off) = make_uint2(a0 | (a1 << 16), a2 | (a3 << 16));
    *(uint2*)(sm + OFF_X2 + byte_off) = make_uint2(b0 | (b1 << 16), b2 | (b3 << 16));
}

__device__ __forceinline__ void ldm_x4(uint32_t& r0, uint32_t& r1, uint32_t& r2,
                                       uint32_t& r3, uint32_t addr) {
    asm volatile("ldmatrix.sync.aligned.m8n8.x4.shared.b16 {%0,%1,%2,%3}, [%4];"
                 : "=r"(r0),"=r"(r1),"=r"(r2),"=r"(r3) : "r"(addr));
}

__device__ __forceinline__ void mma_f16(float* c, const uint32_t* a,
                                        uint32_t b0, uint32_t b1) {
    asm volatile(
        "mma.sync.aligned.m16n8k16.row.col.f32.f16.f16.f32 "
        "{%0,%1,%2,%3}, {%4,%5,%6,%7}, {%8,%9}, {%0,%1,%2,%3};"
        : "+f"(c[0]), "+f"(c[1]), "+f"(c[2]), "+f"(c[3])
        : "r"(a[0]), "r"(a[1]), "r"(a[2]), "r"(a[3]), "r"(b0), "r"(b1));
}

__device__ __forceinline__ void cp16(unsigned dst, const void* src) {
    asm volatile("cp.async.ca.shared.global [%0], [%1], 16;\n" :: "r"(dst), "l"(src));
}
__device__ __forceinline__ void cp_commit() {
    asm volatile("cp.async.commit_group;\n");
}
template <int N>
__device__ __forceinline__ void cp_wait() {
    asm volatile("cp.async.wait_group %0;\n" :: "n"(N));
}

// ------------------------- W pre-split kernel -------------------------
__global__ void wsplit_kernel(const float* __restrict__ W) {
    int i = blockIdx.x * blockDim.x + threadIdx.x;
    if (i < E_DIM * D_DIM) {
        uint32_t a, b;
        split2h(W[i] * W_SCALE, a, b);
        g_ws[i]                 = (uint16_t)a;
        g_ws[E_DIM * D_DIM + i] = (uint16_t)b;
    }
}

// ------------------------- main kernel -------------------------
__global__ __launch_bounds__(THREADS, 2)
void moe_gate_kernel(const float* __restrict__ x,
                     float* __restrict__ out_idx,
                     float* __restrict__ out_w,
                     float* __restrict__ out_aux,
                     int S, int nblocks)
{
    extern __shared__ char smem[];
    __shared__ float sm_cnt[E_DIM];
    __shared__ float sm_ssum[E_DIM];
    __shared__ unsigned int sm_ticket;

    const int tid  = threadIdx.x;
    const int wid  = tid >> 5;
    const int lane = tid & 31;
    const long t0  = (long)blockIdx.x * TPB;
    const unsigned fullmask = 0xffffffffu;
    const uint32_t smem_u = (uint32_t)__cvta_generic_to_shared(smem);

    // warp tile: 16 tokens x ALL 64 experts (two eh half-passes)
    const int m_base = wid * 16;             // wid 0..7

    // ldmatrix per-lane addresses (validated rounds 9-12)
    const uint32_t a_row_off = (uint32_t)(m_base + (lane & 15)) * STR_B
                             + (uint32_t)(lane >> 4) * 16;
    // paired-x4 B base: matrices [nt0 k0][nt0 k1][nt1 k0][nt1 k1]
    const uint32_t b4_base = (uint32_t)((lane & 7) + ((lane >> 4) & 1) * 8) * STR_B
                           + (uint32_t)((lane >> 3) & 1) * 16;

    // x tile: 128 tok x 16 f4 = 2048 f4 -> 8/thread
    const int x_kq  = tid & 15;
    const int x_tok = tid >> 4;          // + 16p

    if (tid < E_DIM) { sm_cnt[tid] = 0.0f; sm_ssum[tid] = 0.0f; }

    float acc[8][4];
#pragma unroll
    for (int n = 0; n < 8; n++)
#pragma unroll
        for (int q = 0; q < 4; q++) acc[n][q] = 0.0f;

    // -------- prologue: chunk 0 --------
    {
        // W: 2 planes x 64 e x 8 seg = 1024 cp16 -> 4/thread
#pragma unroll
        for (int p = 0; p < 4; p++) {
            int idx = tid + THREADS * p;
            int pl = idx >> 9, rem = idx & 511;
            int e = rem >> 3, seg = rem & 7;
            cp16(smem_u + OFF_W1 + pl * WT_B + e * STR_B + seg * 16,
                 &g_ws[pl * (E_DIM * D_DIM) + e * D_DIM + seg * 8]);
        }
        cp_commit();
        float4 xr[8];
#pragma unroll
        for (int p = 0; p < 8; p++)
            xr[p] = *(const float4*)&x[(t0 + x_tok + 16 * p) * D_DIM + x_kq * 4];
#pragma unroll
        for (int p = 0; p < 8; p++)
            store_split_f4(smem, (uint32_t)((x_tok + 16 * p) * STR_B + x_kq * 8), xr[p]);
    }

    // -------- pipelined main loop: one bar per chunk --------
#pragma unroll 1
    for (int c = 0; c < NCHUNK; c++) {
        cp_wait<0>();
        __syncthreads();

        char* bufB = smem + ((c + 1) & 1) * BUF_B;
        const uint32_t bufA_u = smem_u + (uint32_t)((c & 1) * BUF_B);

        float4 xr[8];
        const bool more = (c + 1 < NCHUNK);
        if (more) {
            const int k0n = (c + 1) * KC;
            const unsigned wb = smem_u + (uint32_t)(((c + 1) & 1) * BUF_B) + OFF_W1;
#pragma unroll
            for (int p = 0; p < 4; p++) {
                int idx = tid + THREADS * p;
                int pl = idx >> 9, rem = idx & 511;
                int e = rem >> 3, seg = rem & 7;
                cp16(wb + pl * WT_B + e * STR_B + seg * 16,
                     &g_ws[pl * (E_DIM * D_DIM) + e * D_DIM + k0n + seg * 8]);
            }
            cp_commit();
#pragma unroll
            for (int p = 0; p < 8; p++)
                xr[p] = *(const float4*)&x[(t0 + x_tok + 16 * p) * D_DIM + k0n + x_kq * 4];
        }

        // ---- mma chunk c: 4 fp16 products, two expert half-passes ----
#pragma unroll
        for (int eh = 0; eh < 2; eh++) {
            float cacc[4][4];
#pragma unroll
            for (int nt = 0; nt < 4; nt++)
#pragma unroll
                for (int q = 0; q < 4; q++) cacc[nt][q] = 0.0f;

#pragma unroll
            for (int ks = 0; ks < 4; ks++) {
                const uint32_t a_off = bufA_u + a_row_off + (uint32_t)ks * 32;
                uint32_t a1[4], a2[4];
                ldm_x4(a1[0],a1[1],a1[2],a1[3], a_off + OFF_X1);
                ldm_x4(a2[0],a2[1],a2[2],a2[3], a_off + OFF_X2);
#pragma unroll
                for (int ntp = 0; ntp < 2; ntp++) {
                    const uint32_t b_off = bufA_u + b4_base
                        + (uint32_t)((eh * 32 + ntp * 16)) * STR_B
                        + (uint32_t)ks * 32;
                    uint32_t w1[4], w2[4];
                    ldm_x4(w1[0],w1[1],w1[2],w1[3], b_off + OFF_W1);
                    ldm_x4(w2[0],w2[1],w2[2],w2[3], b_off + OFF_W2);
#pragma unroll
                    for (int h = 0; h < 2; h++) {
                        const int nt = ntp * 2 + h;
                        mma_f16(cacc[nt], a1, w1[2*h], w1[2*h+1]);   // x1*w1
                        mma_f16(cacc[nt], a1, w2[2*h], w2[2*h+1]);   // x1*w2
                        mma_f16(cacc[nt], a2, w1[2*h], w1[2*h+1]);   // x2*w1
                        mma_f16(cacc[nt], a2, w2[2*h], w2[2*h+1]);   // x2*w2
                    }
                }
            }
            // fold chunk sums (plain add; chunk sums are near-exact)
#pragma unroll
            for (int nt = 0; nt < 4; nt++)
#pragma unroll
                for (int q = 0; q < 4; q++)
                    acc[eh * 4 + nt][q] += cacc[nt][q];
        }

        // split + store x(c+1) into next buffer
        if (more) {
#pragma unroll
            for (int p = 0; p < 8; p++)
                store_split_f4(bufB, (uint32_t)((x_tok + 16 * p) * STR_B + x_kq * 8), xr[p]);
        }
    }

    // ---------------- logits -> smem (unscale 2^-16) ----------------
    __syncthreads();
    float* logit = (float*)smem;
    {
        const int r0 = m_base + (lane >> 2);
        const int c0 = (lane & 3) * 2;
#pragma unroll
        for (int n = 0; n < 8; n++) {
            const int col = n * 8 + c0;       // n = eh*4 + nt covers 0..63
            *(float2*)&logit[r0 * LOG_STR + col] =
                make_float2(acc[n][0] * W_UNSCALE, acc[n][1] * W_UNSCALE);
            *(float2*)&logit[(r0 + 8) * LOG_STR + col] =
                make_float2(acc[n][2] * W_UNSCALE, acc[n][3] * W_UNSCALE);
        }
    }
    __syncthreads();

    // ---------------- epilogue: softmax + top-8 + stats (proven) ------------
    const int et = tid & 15;      // expert lane (experts et + 16r)
    const int tt = tid >> 4;      // token thread 0..15 (tokens tt + 16j)
    float loc_ssum[4] = {0.f, 0.f, 0.f, 0.f};

#pragma unroll 1
    for (int j = 0; j < 8; j++) {
        const int token = tt + 16 * j;
        float a[4];
#pragma unroll
        for (int r = 0; r < 4; r++)
            a[r] = logit[token * LOG_STR + et + 16 * r];

        float m = a[0];
#pragma unroll
        for (int r = 1; r < 4; r++) m = fmaxf(m, a[r]);
#pragma unroll
        for (int d = 1; d < 16; d <<= 1)
            m = fmaxf(m, __shfl_xor_sync(fullmask, m, d));

        float sc[4];
        float s = 0.0f;
#pragma unroll
        for (int r = 0; r < 4; r++) { sc[r] = expf(a[r] - m); s += sc[r]; }
#pragma unroll
        for (int d = 1; d < 16; d <<= 1)
            s += __shfl_xor_sync(fullmask, s, d);
#pragma unroll
        for (int r = 0; r < 4; r++) { sc[r] = sc[r] / s; loc_ssum[r] += sc[r]; }

        float tv[TOPK]; int ti[TOPK];
#pragma unroll 1
        for (int it = 0; it < TOPK; it++) {
            float bv = -1.0f; int bi = E_DIM;
#pragma unroll
            for (int r = 0; r < 4; r++)
                if (sc[r] > bv) { bv = sc[r]; bi = et + 16 * r; }
#pragma unroll
            for (int d = 1; d < 16; d <<= 1) {
                float ov = __shfl_xor_sync(fullmask, bv, d);
                int   oi = __shfl_xor_sync(fullmask, bi, d);
                if (ov > bv || (ov == bv && oi < bi)) { bv = ov; bi = oi; }
            }
            if ((bi & 15) == et) sc[bi >> 4] = -1.0f;
            tv[it] = bv; ti[it] = bi;
        }

        if (et == 0) {
            float wsum = 0.0f;
#pragma unroll
            for (int it = 0; it < TOPK; it++) wsum += tv[it];
            wsum += EPS_R;
            long t = t0 + token;
#pragma unroll
            for (int it = 0; it < TOPK; it++) {
                out_idx[t * TOPK + it] = (float)ti[it];
                out_w  [t * TOPK + it] = tv[it] / wsum;
                atomicAdd(&sm_cnt[ti[it]], 1.0f);
            }
        }
    }

#pragma unroll
    for (int r = 0; r < 4; r++)
        atomicAdd(&sm_ssum[et + 16 * r], loc_ssum[r]);
    __syncthreads();

    if (tid < E_DIM) {
        int b = (int)(t0 / (long)S);      // tile batch-aligned (128 | 8192)
        atomicAdd(&g_ce[b * E_DIM + tid],   sm_cnt[tid]);
        atomicAdd(&g_ssum[b * E_DIM + tid], sm_ssum[tid]);
    }

    // ---------------- fused aux finalization (last CTA) ----------------
    __threadfence();
    if (tid == 0) sm_ticket = atomicAdd(&g_count, 1u);
    __syncthreads();

    if (sm_ticket == (unsigned)(nblocks - 1)) {
        __threadfence();
        const volatile float* ce = g_ce;
        const volatile float* ss = g_ssum;
        float v = (tid < B_DIM * E_DIM) ? ce[tid] * ss[tid] : 0.0f;
        float* red = (float*)smem;
        red[tid] = v;
        __syncthreads();
        for (int off = 128; off > 0; off >>= 1) {
            if (tid < off) red[tid] += red[tid + off];
            __syncthreads();
        }
        if (tid == 0)
            out_aux[0] = red[0] / (float)S / (float)B_DIM * ALPHA;
        if (tid < B_DIM * E_DIM) { g_ce[tid] = 0.0f; g_ssum[tid] = 0.0f; }
        if (tid == 0) g_count = 0u;
    }
}

extern "C" void kernel_launch(void* const* d_in, const int* in_sizes, int n_in,
                              void* d_out, int out_size) {
    const float* x = (const float*)d_in[0];
    const float* W = (const float*)d_in[1];
    const int T = in_sizes[0] / D_DIM;     // 32768
    const int S = T / B_DIM;               // 8192
    const int nblocks = T / TPB;           // 256 (one wave at 2 CTA/SM)

    float* out     = (float*)d_out;
    float* out_idx = out;                         // [T,8] indices as float
    float* out_w   = out + (size_t)T * TOPK;      // [T,8] weights
    float* out_aux = out + (out_size - 1);        // scalar aux loss

    wsplit_kernel<<<(E_DIM * D_DIM + 1023) / 1024, 1024>>>(W);

    cudaFuncSetAttribute(moe_gate_kernel,
                         cudaFuncAttributeMaxDynamicSharedMemorySize, SMEM_BYTES);
    moe_gate_kernel<<<nblocks, THREADS, SMEM_BYTES>>>(x, out_idx, out_w,
                                                      out_aux, S, nblocks);
}

// round 15
// speedup vs baseline: 1.3105x; 1.3105x over previous
#include <cuda_runtime.h>
#include <cuda_fp16.h>
#include <cstdint>

// Problem constants
#define D_DIM   1024
#define E_DIM   64
#define TOPK    8
#define B_DIM   4
#define ALPHA   0.1f
#define EPS_R   1e-20f

#define THREADS 256
#define TPB     64               // tokens per tile
#define NTILES  2                // tiles per CTA
#define KC      64               // K per chunk
#define NCHUNK  (D_DIM / KC)     // 16

#define W_SCALE    65536.0f      // 2^16: keeps w2 split term normal in fp16
#define W_UNSCALE  1.52587890625e-05f   // 2^-16 (exact)

// smem: fp16 tiles, 64 cols used, row stride 72 el = 144 B (conflict-free ldmatrix)
#define STR_B   144
#define XT_B    (TPB * STR_B)         // 9216
#define WT_B    (E_DIM * STR_B)       // 9216
#define OFF_X1  0
#define OFF_X2  (OFF_X1 + XT_B)
#define OFF_W1  (OFF_X2 + XT_B)
#define OFF_W2  (OFF_W1 + WT_B)
#define BUF_B   (OFF_W2 + WT_B)       // 36864 per buffer
#define SMEM_BYTES (2 * BUF_B)        // 73728 per CTA (x2 CTA/SM = 144KB)
#define LOG_STR 66                    // padded logits row (floats)

// device-global scratch (static — no allocation)
__device__ uint16_t g_ws[2 * E_DIM * D_DIM];   // pre-split scaled W (fp16 bits)
__device__ float g_ce[B_DIM * E_DIM];
__device__ float g_ssum[B_DIM * E_DIM];
__device__ unsigned int g_count;

// ------------------------- helpers -------------------------
__device__ __forceinline__ void split2h(float v, uint32_t& a, uint32_t& b) {
    __half h1 = __float2half_rn(v);
    float r = v - __half2float(h1);
    __half h2 = __float2half_rn(r);
    a = __half_as_ushort(h1);
    b = __half_as_ushort(h2);
}

// packed fp16x2 split of a float4 (exact residuals)
__device__ __forceinline__ void store_split_f4(char* sm, uint32_t byte_off, float4 v) {
    uint32_t h1a, h1b;
    asm("cvt.rn.f16x2.f32 %0, %1, %2;" : "=r"(h1a) : "f"(v.y), "f"(v.x));
    asm("cvt.rn.f16x2.f32 %0, %1, %2;" : "=r"(h1b) : "f"(v.w), "f"(v.z));
    __half2 p1a = *(__half2*)&h1a;
    __half2 p1b = *(__half2*)&h1b;
    float r0 = v.x - __low2float(p1a);
    float r1 = v.y - __high2float(p1a);
    float r2 = v.z - __low2float(p1b);
    float r3 = v.w - __high2float(p1b);
    uint32_t h2a, h2b;
    asm("cvt.rn.f16x2.f32 %0, %1, %2;" : "=r"(h2a) : "f"(r1), "f"(r0));
    asm("cvt.rn.f16x2.f32 %0, %1, %2;" : "=r"(h2b) : "f"(r3), "f"(r2));
    *(uint2*)(sm + OFF_X1 + byte_off) = make_uint2(h1a, h1b);
    *(uint2*)(sm + OFF_X2 + byte_off) = make_uint2(h2a, h2b);
}

__device__ __forceinline__ void ldm_x4(uint32_t& r0, uint32_t& r1, uint32_t& r2,
                                       uint32_t& r3, uint32_t addr) {
    asm volatile("ldmatrix.sync.aligned.m8n8.x4.shared.b16 {%0,%1,%2,%3}, [%4];"
                 : "=r"(r0),"=r"(r1),"=r"(r2),"=r"(r3) : "r"(addr));
}

__device__ __forceinline__ void mma_f16(float* c, const uint32_t* a,
                                        uint32_t b0, uint32_t b1) {
    asm volatile(
        "mma.sync.aligned.m16n8k16.row.col.f32.f16.f16.f32 "
        "{%0,%1,%2,%3}, {%4,%5,%6,%7}, {%8,%9}, {%0,%1,%2,%3};"
        : "+f"(c[0]), "+f"(c[1]), "+f"(c[2]), "+f"(c[3])
        : "r"(a[0]), "r"(a[1]), "r"(a[2]), "r"(a[3]), "r"(b0), "r"(b1));
}

__device__ __forceinline__ void cp16(unsigned dst, const void* src) {
    asm volatile("cp.async.ca.shared.global [%0], [%1], 16;\n" :: "r"(dst), "l"(src));
}
__device__ __forceinline__ void cp_commit() {
    asm volatile("cp.async.commit_group;\n");
}
template <int N>
__device__ __forceinline__ void cp_wait() {
    asm volatile("cp.async.wait_group %0;\n" :: "n"(N));
}

// ------------------------- W pre-split kernel -------------------------
__global__ void wsplit_kernel(const float* __restrict__ W) {
    int i = blockIdx.x * blockDim.x + threadIdx.x;
    if (i < E_DIM * D_DIM) {
        uint32_t a, b;
        split2h(W[i] * W_SCALE, a, b);
        g_ws[i]                 = (uint16_t)a;
        g_ws[E_DIM * D_DIM + i] = (uint16_t)b;
    }
}

// ------------------------- main kernel -------------------------
__global__ __launch_bounds__(THREADS, 2)
void moe_gate_kernel(const float* __restrict__ x,
                     float* __restrict__ out_idx,
                     float* __restrict__ out_w,
                     float* __restrict__ out_aux,
                     int S, int nblocks)
{
    extern __shared__ char smem[];
    __shared__ float sm_cnt[E_DIM];
    __shared__ float sm_ssum[E_DIM];
    __shared__ unsigned int sm_ticket;

    const int tid  = threadIdx.x;
    const int wid  = tid >> 5;
    const int lane = tid & 31;
    const unsigned fullmask = 0xffffffffu;
    const uint32_t smem_u = (uint32_t)__cvta_generic_to_shared(smem);

    // warp tile: 16 tokens x 32 experts (4 token groups x 2 expert halves)
    const int tok_grp = wid >> 1;
    const int eh      = wid & 1;
    const int m_base  = tok_grp * 16;

    // ldmatrix per-lane addresses (validated rounds 9-12)
    const uint32_t a_row_off = (uint32_t)(m_base + (lane & 15)) * STR_B
                             + (uint32_t)(lane >> 4) * 16;
    const uint32_t b4_off = (uint32_t)((lane & 7) + ((lane >> 4) & 1) * 8
                                       + eh * 32) * STR_B
                          + (uint32_t)((lane >> 3) & 1) * 16;

    // x tile: 64 tok x 16 f4 = 1024 f4 -> 4/thread
    const int x_kq  = tid & 15;
    const int x_tok = tid >> 4;          // + 16p

    // W cp: 2 planes x 64 e x 8 seg = 1024 cp16 -> 4/thread (hoisted bases)
    const uint16_t* w_src[4];
    uint32_t w_dst_off[4];
#pragma unroll
    for (int p = 0; p < 4; p++) {
        int idx = tid + THREADS * p;
        int pl = idx >> 9, rem = idx & 511;
        int e = rem >> 3, seg = rem & 7;
        w_src[p] = &g_ws[pl * (E_DIM * D_DIM) + e * D_DIM + seg * 8];
        w_dst_off[p] = (uint32_t)(OFF_W1 + pl * WT_B + e * STR_B + seg * 16);
    }

#pragma unroll 1
    for (int tile = 0; tile < NTILES; tile++) {
        const long t0 = (long)(blockIdx.x + tile * nblocks) * TPB;

        if (tid < E_DIM) { sm_cnt[tid] = 0.0f; sm_ssum[tid] = 0.0f; }

        float acc[4][4];
#pragma unroll
        for (int nt = 0; nt < 4; nt++)
#pragma unroll
            for (int q = 0; q < 4; q++) acc[nt][q] = 0.0f;

        // -------- prologue: chunk 0 --------
        {
#pragma unroll
            for (int p = 0; p < 4; p++)
                cp16(smem_u + w_dst_off[p], w_src[p]);
            cp_commit();
            float4 xr[4];
#pragma unroll
            for (int p = 0; p < 4; p++)
                xr[p] = *(const float4*)&x[(t0 + x_tok + 16 * p) * D_DIM + x_kq * 4];
#pragma unroll
            for (int p = 0; p < 4; p++)
                store_split_f4(smem, (uint32_t)((x_tok + 16 * p) * STR_B + x_kq * 8), xr[p]);
        }

        // -------- pipelined main loop: one bar per chunk --------
#pragma unroll 1
        for (int c = 0; c < NCHUNK; c++) {
            cp_wait<0>();
            __syncthreads();

            char* bufB = smem + ((c + 1) & 1) * BUF_B;
            const uint32_t bufA_u = smem_u + (uint32_t)((c & 1) * BUF_B);

            float4 xr[4];
            const bool more = (c + 1 < NCHUNK);
            if (more) {
                const int k0n = (c + 1) * KC;
                const uint32_t buf_off = (uint32_t)(((c + 1) & 1) * BUF_B);
#pragma unroll
                for (int p = 0; p < 4; p++)
                    cp16(smem_u + buf_off + w_dst_off[p], w_src[p] + k0n);
                cp_commit();
#pragma unroll
                for (int p = 0; p < 4; p++)
                    xr[p] = *(const float4*)&x[(t0 + x_tok + 16 * p) * D_DIM + k0n + x_kq * 4];
            }

            // ---- mma chunk c: 4 fp16 products, 2 independent accumulator sets ----
            float caccW1[4][4], caccW2[4][4];
#pragma unroll
            for (int nt = 0; nt < 4; nt++)
#pragma unroll
                for (int q = 0; q < 4; q++) { caccW1[nt][q] = 0.0f; caccW2[nt][q] = 0.0f; }

#pragma unroll
            for (int ks = 0; ks < 4; ks++) {
                const uint32_t a_off = bufA_u + a_row_off + (uint32_t)ks * 32;
                uint32_t a1[4], a2[4];
                ldm_x4(a1[0],a1[1],a1[2],a1[3], a_off + OFF_X1);
                ldm_x4(a2[0],a2[1],a2[2],a2[3], a_off + OFF_X2);
#pragma unroll
                for (int ntp = 0; ntp < 2; ntp++) {
                    const uint32_t b_off = bufA_u + b4_off
                        + (uint32_t)(ntp * 16) * STR_B + (uint32_t)ks * 32;
                    uint32_t w1[4], w2[4];
                    ldm_x4(w1[0],w1[1],w1[2],w1[3], b_off + OFF_W1);
                    ldm_x4(w2[0],w2[1],w2[2],w2[3], b_off + OFF_W2);
#pragma unroll
                    for (int h = 0; h < 2; h++) {
                        const int nt = ntp * 2 + h;
                        // chain A (w1 plane) and chain B (w2 plane) independent
                        mma_f16(caccW1[nt], a1, w1[2*h], w1[2*h+1]);   // x1*w1
                        mma_f16(caccW2[nt], a1, w2[2*h], w2[2*h+1]);   // x1*w2
                        mma_f16(caccW1[nt], a2, w1[2*h], w1[2*h+1]);   // x2*w1
                        mma_f16(caccW2[nt], a2, w2[2*h], w2[2*h+1]);   // x2*w2
                    }
                }
            }

            // fold chunk sums (plain add; proven safe in round 14)
#pragma unroll
            for (int nt = 0; nt < 4; nt++)
#pragma unroll
                for (int q = 0; q < 4; q++)
                    acc[nt][q] += caccW1[nt][q] + caccW2[nt][q];

            // split + store x(c+1) into next buffer
            if (more) {
#pragma unroll
                for (int p = 0; p < 4; p++)
                    store_split_f4(bufB, (uint32_t)((x_tok + 16 * p) * STR_B + x_kq * 8), xr[p]);
            }
        }

        // ---------------- logits -> smem (unscale 2^-16) ----------------
        __syncthreads();
        float* logit = (float*)smem;
        {
            const int r0 = m_base + (lane >> 2);
            const int c0 = (lane & 3) * 2;
#pragma unroll
            for (int nt = 0; nt < 4; nt++) {
                const int col = eh * 32 + nt * 8 + c0;
                *(float2*)&logit[r0 * LOG_STR + col] =
                    make_float2(acc[nt][0] * W_UNSCALE, acc[nt][1] * W_UNSCALE);
                *(float2*)&logit[(r0 + 8) * LOG_STR + col] =
                    make_float2(acc[nt][2] * W_UNSCALE, acc[nt][3] * W_UNSCALE);
            }
        }
        __syncthreads();

        // ---------------- epilogue: softmax + top-8 + stats ----------------
        const int et = tid & 15;      // expert lane (experts et + 16r)
        const int tt = tid >> 4;      // token thread 0..15 (tokens tt + 16j)
        float loc_ssum[4] = {0.f, 0.f, 0.f, 0.f};

#pragma unroll 1
        for (int j = 0; j < 4; j++) {
            const int token = tt + 16 * j;
            float a[4];
#pragma unroll
            for (int r = 0; r < 4; r++)
                a[r] = logit[token * LOG_STR + et + 16 * r];

            float m = a[0];
#pragma unroll
            for (int r = 1; r < 4; r++) m = fmaxf(m, a[r]);
#pragma unroll
            for (int d = 1; d < 16; d <<= 1)
                m = fmaxf(m, __shfl_xor_sync(fullmask, m, d));

            float sc[4];
            float s = 0.0f;
#pragma unroll
            for (int r = 0; r < 4; r++) { sc[r] = expf(a[r] - m); s += sc[r]; }
#pragma unroll
            for (int d = 1; d < 16; d <<= 1)
                s += __shfl_xor_sync(fullmask, s, d);
#pragma unroll
            for (int r = 0; r < 4; r++) { sc[r] = sc[r] / s; loc_ssum[r] += sc[r]; }

            float tv[TOPK]; int ti[TOPK];
#pragma unroll 1
            for (int it = 0; it < TOPK; it++) {
                float bv = -1.0f; int bi = E_DIM;
#pragma unroll
                for (int r = 0; r < 4; r++)
                    if (sc[r] > bv) { bv = sc[r]; bi = et + 16 * r; }
#pragma unroll
                for (int d = 1; d < 16; d <<= 1) {
                    float ov = __shfl_xor_sync(fullmask, bv, d);
                    int   oi = __shfl_xor_sync(fullmask, bi, d);
                    if (ov > bv || (ov == bv && oi < bi)) { bv = ov; bi = oi; }
                }
                if ((bi & 15) == et) sc[bi >> 4] = -1.0f;
                tv[it] = bv; ti[it] = bi;
            }

            if (et == 0) {
                float wsum = 0.0f;
#pragma unroll
                for (int it = 0; it < TOPK; it++) wsum += tv[it];
                wsum += EPS_R;
                long t = t0 + token;
#pragma unroll
                for (int it = 0; it < TOPK; it++) {
                    out_idx[t * TOPK + it] = (float)ti[it];
                    out_w  [t * TOPK + it] = tv[it] / wsum;
                    atomicAdd(&sm_cnt[ti[it]], 1.0f);
                }
            }
        }

#pragma unroll
        for (int r = 0; r < 4; r++)
            atomicAdd(&sm_ssum[et + 16 * r], loc_ssum[r]);
        __syncthreads();

        if (tid < E_DIM) {
            int b = (int)(t0 / (long)S);     // per-tile batch (64 | 8192)
            atomicAdd(&g_ce[b * E_DIM + tid],   sm_cnt[tid]);
            atomicAdd(&g_ssum[b * E_DIM + tid], sm_ssum[tid]);
        }
        __syncthreads();
    }

    // ---------------- fused aux finalization (last CTA) ----------------
    __threadfence();
    if (tid == 0) sm_ticket = atomicAdd(&g_count, 1u);
    __syncthreads();

    if (sm_ticket == (unsigned)(nblocks - 1)) {
        __threadfence();
        const volatile float* ce = g_ce;
        const volatile float* ss = g_ssum;
        float v = (tid < B_DIM * E_DIM) ? ce[tid] * ss[tid] : 0.0f;
        float* red = (float*)smem;
        red[tid] = v;
        __syncthreads();
        for (int off = 128; off > 0; off >>= 1) {
            if (tid < off) red[tid] += red[tid + off];
            __syncthreads();
        }
        if (tid == 0)
            out_aux[0] = red[0] / (float)S / (float)B_DIM * ALPHA;
        if (tid < B_DIM * E_DIM) { g_ce[tid] = 0.0f; g_ssum[tid] = 0.0f; }
        if (tid == 0) g_count = 0u;
    }
}

extern "C" void kernel_launch(void* const* d_in, const int* in_sizes, int n_in,
                              void* d_out, int out_size) {
    const float* x = (const float*)d_in[0];
    const float* W = (const float*)d_in[1];
    const int T = in_sizes[0] / D_DIM;       // 32768
    const int S = T / B_DIM;                 // 8192
    const int nblocks = T / (TPB * NTILES);  // 256

    float* out     = (float*)d_out;
    float* out_idx = out;                         // [T,8] indices as float
    float* out_w   = out + (size_t)T * TOPK;      // [T,8] weights
    float* out_aux = out + (out_size - 1);        // scalar aux loss

    wsplit_kernel<<<(E_DIM * D_DIM + 1023) / 1024, 1024>>>(W);

    cudaFuncSetAttribute(moe_gate_kernel,
                         cudaFuncAttributeMaxDynamicSharedMemorySize, SMEM_BYTES);
    moe_gate_kernel<<<nblocks, THREADS, SMEM_BYTES>>>(x, out_idx, out_w,
                                                      out_aux, S, nblocks);
}